// round 13
// baseline (speedup 1.0000x reference)
#include <cuda_runtime.h>
#include <cstdint>

#define DEVI static __device__ __forceinline__

namespace {
constexpr int B_ = 256;   // batch
constexpr int T_ = 256;   // time
constexpr int D_ = 64;    // input dim
constexpr int H_ = 512;   // hidden
constexpr int FOURH = 4 * H_;          // 2048
constexpr int M_ALL = B_ * T_;         // 65536

// step-kernel tiling: 4 batch-groups x 64 rows, 32 j-tiles x 16 cols
constexpr int MB = 64;                 // batch rows per block
constexpr int WJ = 16;                 // hidden cols per block (per gate)
constexpr int GRID_S = 128;            // 4 * 32

constexpr int G_STRIDE = 17;

// step-kernel dynamic smem: 4-stage pipeline, W and A chunks 64x32 (+4 pad)
constexpr int ST_ROWS = 64;            // rows per stage (A: 64 batch; W: 4g x 16 cols)
constexpr int ST_FLOATS = ST_ROWS * 36;                 // 2304 per stage
constexpr int SW_OFF = 0;                               // [4][64][36]
constexpr int SA_OFF = 4 * ST_FLOATS;                   // 9216
constexpr int STEP_SMEM_FLOATS = SA_OFF + 4 * ST_FLOATS;  // 18432
constexpr int STEP_SMEM_BYTES = STEP_SMEM_FLOATS * 4;     // 73728 B
}

// ---------- scratch (device globals; NO allocations anywhere) ----------
__device__ float g_xw[(size_t)M_ALL * FOURH];  // input projections, layout [t][B][4H]
__device__ float g_h1[(size_t)M_ALL * H_];     // layer-0 hidden sequence [b][t][H]
__device__ float g_hbuf[2][B_ * H_];           // ping-pong hidden state
__device__ float g_c[B_ * H_];                 // cell state
__device__ float g_sum[B_ * H_];               // sum over t of layer-1 h
__device__ float g_head[B_ * 256];             // shared-head output

// ---------- helpers ----------
DEVI float tf32r(float x) {
    unsigned u;
    asm("cvt.rna.tf32.f32 %0, %1;" : "=r"(u) : "f"(x));
    return __uint_as_float(u);
}

DEVI void mma8(float* c, const unsigned* a, unsigned b0, unsigned b1) {
    asm volatile(
        "mma.sync.aligned.m16n8k8.row.col.f32.tf32.tf32.f32 "
        "{%0,%1,%2,%3}, {%4,%5,%6,%7}, {%8,%9}, {%0,%1,%2,%3};\n"
        : "+f"(c[0]), "+f"(c[1]), "+f"(c[2]), "+f"(c[3])
        : "r"(a[0]), "r"(a[1]), "r"(a[2]), "r"(a[3]), "r"(b0), "r"(b1));
}

DEVI void cpasync16(void* dst_smem, const void* src) {
    unsigned d = (unsigned)__cvta_generic_to_shared(dst_smem);
    asm volatile("cp.async.cg.shared.global [%0], [%1], 16;\n" :: "r"(d), "l"(src));
}
DEVI void cpcommit() { asm volatile("cp.async.commit_group;\n" ::: "memory"); }
DEVI void cpwait2() { asm volatile("cp.async.wait_group 2;\n" ::: "memory"); }
DEVI void cpwait0() { asm volatile("cp.async.wait_group 0;\n" ::: "memory"); }

DEVI float sigmoidf_(float x) { return 1.0f / (1.0f + __expf(-x)); }

DEVI float tanhf_(float x) {
    x = fminf(fmaxf(x, -15.0f), 15.0f);
    float e = __expf(-2.0f * x);
    return (1.0f - e) / (1.0f + e);
}

// ---------- zero state ----------
__global__ void zero_state_kernel() {
    int i = blockIdx.x * blockDim.x + threadIdx.x;
    if (i < B_ * H_) {
        g_hbuf[0][i] = 0.0f;
        g_c[i] = 0.0f;
        g_sum[i] = 0.0f;
    }
}

// ---------- big input-projection GEMM ----------
// out[t][B][4H] = A[M][K] @ W[4H][K]^T + bias  (A rows m = b*T+t)
// Block tile 128x64, 256 threads (8 warps, 4x2 of 32x32), tf32 mma, K chunk 32.
__global__ void __launch_bounds__(256) gemm_xw_kernel(
    const float* __restrict__ Aext, int useH1,
    const float* __restrict__ W, const float* __restrict__ bias, int K)
{
    __shared__ float As[128][36];
    __shared__ float Bs[64][36];
    const float* __restrict__ A = useH1 ? g_h1 : Aext;

    const int tid = threadIdx.x;
    const int lane = tid & 31;
    const int w = tid >> 5;
    const int wm = w >> 1, wn = w & 1;
    const int grp = lane >> 2, tig = lane & 3;
    const int m0 = blockIdx.x * 128;
    const int j0 = blockIdx.y * 64;

    float acc[2][4][4] = {};

    for (int kc = 0; kc < K; kc += 32) {
        __syncthreads();
#pragma unroll
        for (int i = 0; i < 4; i++) {               // A tile 128x32
            int q = tid + 256 * i;
            int r = q >> 3, c4 = (q & 7) << 2;
            float4 v = *reinterpret_cast<const float4*>(&A[(size_t)(m0 + r) * K + kc + c4]);
            As[r][c4 + 0] = tf32r(v.x);
            As[r][c4 + 1] = tf32r(v.y);
            As[r][c4 + 2] = tf32r(v.z);
            As[r][c4 + 3] = tf32r(v.w);
        }
#pragma unroll
        for (int i = 0; i < 2; i++) {               // W tile 64x32
            int q = tid + 256 * i;
            int r = q >> 3, c4 = (q & 7) << 2;
            float4 v = *reinterpret_cast<const float4*>(&W[(size_t)(j0 + r) * K + kc + c4]);
            Bs[r][c4 + 0] = tf32r(v.x);
            Bs[r][c4 + 1] = tf32r(v.y);
            Bs[r][c4 + 2] = tf32r(v.z);
            Bs[r][c4 + 3] = tf32r(v.w);
        }
        __syncthreads();

#pragma unroll
        for (int ks = 0; ks < 4; ks++) {
            unsigned a[2][4];
#pragma unroll
            for (int mt = 0; mt < 2; mt++) {
                int rb = wm * 32 + mt * 16;
                a[mt][0] = __float_as_uint(As[rb + grp][ks * 8 + tig]);
                a[mt][1] = __float_as_uint(As[rb + grp + 8][ks * 8 + tig]);
                a[mt][2] = __float_as_uint(As[rb + grp][ks * 8 + tig + 4]);
                a[mt][3] = __float_as_uint(As[rb + grp + 8][ks * 8 + tig + 4]);
            }
#pragma unroll
            for (int nt = 0; nt < 4; nt++) {
                int cb = wn * 32 + nt * 8;
                unsigned b0 = __float_as_uint(Bs[cb + grp][ks * 8 + tig]);
                unsigned b1 = __float_as_uint(Bs[cb + grp][ks * 8 + tig + 4]);
                mma8(acc[0][nt], a[0], b0, b1);
                mma8(acc[1][nt], a[1], b0, b1);
            }
        }
    }

    // epilogue: + bias, permuted write to [t][B][4H]
#pragma unroll
    for (int mt = 0; mt < 2; mt++) {
#pragma unroll
        for (int nt = 0; nt < 4; nt++) {
            int row = m0 + wm * 32 + mt * 16 + grp;
            int col = j0 + wn * 32 + nt * 8 + tig * 2;
            float bv0 = bias[col], bv1 = bias[col + 1];
#pragma unroll
            for (int half = 0; half < 2; half++) {
                int r = row + half * 8;
                int t = r & (T_ - 1), b = r >> 8;
                size_t o = ((size_t)t * B_ + b) * FOURH + col;
                g_xw[o] = acc[mt][nt][half * 2 + 0] + bv0;
                g_xw[o + 1] = acc[mt][nt][half * 2 + 1] + bv1;
            }
        }
    }
}

// ---------- one LSTM timestep (4-stage cp.async pipeline, no inter-block sync) ----------
// Grid 128 blocks: bg = bid>>5 (64 batch rows), jt = bid&31 (16 hidden cols, all 4 gates).
// 256 threads / 8 warps: warp w -> gate (w&3), batch half (w>>2).
// 16 K-chunks stream through a 4-stage pipeline with wait_group 2 (3 chunks of
// lookahead ~768 cyc > L2 latency) and ONE __syncthreads per chunk. tf32 mma on raw
// fp32 bits (HW reads bits[31:13]).
__global__ void __launch_bounds__(256) lstm_step_kernel(
    const float* __restrict__ Whh, int t, int mode)  // mode 0: write g_h1; 1: accumulate sum
{
    extern __shared__ __align__(16) float smf[];
    float* const SW = smf + SW_OFF;   // [4][64][36]: stage, row (g*16+n), k
    float* const SA = smf + SA_OFF;   // [4][64][36]: stage, batch row, k

    const int tid = threadIdx.x;
    const int lane = tid & 31;
    const int w = tid >> 5;
    const int grp = lane >> 2, tig = lane & 3;
    const int bg = blockIdx.x >> 5;
    const int jt = blockIdx.x & 31;
    const int m0 = bg * MB;
    const int j0 = jt * WJ;
    const int g = w & 3;
    const int mb = (w >> 2) * 32;

    const float* __restrict__ hprev = g_hbuf[t & 1];
    float* __restrict__ hnext = g_hbuf[(t + 1) & 1];

    // stage loader: stage s in [0,4), K offset kc. 4 cp.async per thread (A: 2, W: 2).
    auto load_chunk = [&](int s, int kc) {
#pragma unroll
        for (int i = 0; i < 2; i++) {
            int p = tid + 256 * i;
            int row = p >> 3, seg = (p & 7) << 2;
            cpasync16(&SA[(s * ST_ROWS + row) * 36 + seg],
                      &hprev[(m0 + row) * H_ + kc + seg]);
        }
#pragma unroll
        for (int i = 0; i < 2; i++) {
            int p = tid + 256 * i;
            int rw = p >> 3, seg = (p & 7) << 2;
            int g2 = rw >> 4, n = rw & 15;
            cpasync16(&SW[(s * ST_ROWS + rw) * 36 + seg],
                      &Whh[(size_t)(g2 * H_ + j0 + n) * H_ + kc + seg]);
        }
    };

    load_chunk(0, 0);  cpcommit();
    load_chunk(1, 32); cpcommit();
    load_chunk(2, 64); cpcommit();

    float acc[2][2][4] = {};

    for (int ci = 0; ci < 16; ci++) {
        const int s = ci & 3;
        cpwait2();              // chunk ci resident (<=2 younger groups in flight)
        __syncthreads();        // all warps done with the stage being refilled below
        if (ci + 3 < 16) load_chunk((ci + 3) & 3, (ci + 3) * 32);
        cpcommit();             // empty tail groups keep wait arithmetic uniform

        const float* Ab = &SA[s * ST_ROWS * 36];
        const float* Wb = &SW[(s * ST_ROWS + g * WJ) * 36];
#pragma unroll
        for (int ks = 0; ks < 4; ks++) {
            unsigned a[2][4];
#pragma unroll
            for (int mt = 0; mt < 2; mt++) {
                int rb = mb + mt * 16;
                a[mt][0] = __float_as_uint(Ab[(rb + grp) * 36 + ks * 8 + tig]);
                a[mt][1] = __float_as_uint(Ab[(rb + grp + 8) * 36 + ks * 8 + tig]);
                a[mt][2] = __float_as_uint(Ab[(rb + grp) * 36 + ks * 8 + tig + 4]);
                a[mt][3] = __float_as_uint(Ab[(rb + grp + 8) * 36 + ks * 8 + tig + 4]);
            }
#pragma unroll
            for (int nt = 0; nt < 2; nt++) {
                unsigned b0 = __float_as_uint(Wb[(nt * 8 + grp) * 36 + ks * 8 + tig]);
                unsigned b1 = __float_as_uint(Wb[(nt * 8 + grp) * 36 + ks * 8 + tig + 4]);
                mma8(acc[0][nt], a[0], b0, b1);
                mma8(acc[1][nt], a[1], b0, b1);
            }
        }
    }
    cpwait0();   // drain empty tail groups

    // gate exchange: G aliases SA stages 0-1 (4352 floats <= 2*2304).
    // Stages 0/1 were last read at ci=12/13; every warp has passed the ci=14/15
    // top-of-loop __syncthreads, so both stages are dead for all warps.
    float* const Gsm = &SA[0];
#pragma unroll
    for (int mt = 0; mt < 2; mt++) {
#pragma unroll
        for (int nt = 0; nt < 2; nt++) {
            int r0 = mb + mt * 16 + grp;
            int c = nt * 8 + tig * 2;
            Gsm[(g * MB + r0) * G_STRIDE + c] = acc[mt][nt][0];
            Gsm[(g * MB + r0) * G_STRIDE + c + 1] = acc[mt][nt][1];
            Gsm[(g * MB + r0 + 8) * G_STRIDE + c] = acc[mt][nt][2];
            Gsm[(g * MB + r0 + 8) * G_STRIDE + c + 1] = acc[mt][nt][3];
        }
    }
    __syncthreads();

    // fused activation + cell update: 4 cells per thread
    const int b_loc = tid >> 2;
    const int hc0 = (tid & 3) * 4;
    const int b = m0 + b_loc;
    const size_t xo = ((size_t)t * B_ + b) * FOURH + j0 + hc0;
    const float4 xi  = __ldg(reinterpret_cast<const float4*>(&g_xw[xo]));
    const float4 xf  = __ldg(reinterpret_cast<const float4*>(&g_xw[xo + H_]));
    const float4 xg  = __ldg(reinterpret_cast<const float4*>(&g_xw[xo + 2 * H_]));
    const float4 xo4 = __ldg(reinterpret_cast<const float4*>(&g_xw[xo + 3 * H_]));
    float4 c4 = *reinterpret_cast<float4*>(&g_c[b * H_ + j0 + hc0]);

    float gi[4] = {xi.x, xi.y, xi.z, xi.w};
    float gf[4] = {xf.x, xf.y, xf.z, xf.w};
    float gg[4] = {xg.x, xg.y, xg.z, xg.w};
    float go[4] = {xo4.x, xo4.y, xo4.z, xo4.w};
    float cr[4] = {c4.x, c4.y, c4.z, c4.w};
    float hv[4];
#pragma unroll
    for (int j = 0; j < 4; j++) {
        int gb = b_loc * G_STRIDE + hc0 + j;
        float ii = sigmoidf_(Gsm[gb] + gi[j]);
        float ff = sigmoidf_(Gsm[MB * G_STRIDE + gb] + gf[j]);
        float gt = tanhf_(Gsm[2 * MB * G_STRIDE + gb] + gg[j]);
        float oo = sigmoidf_(Gsm[3 * MB * G_STRIDE + gb] + go[j]);
        cr[j] = ff * cr[j] + ii * gt;
        hv[j] = oo * tanhf_(cr[j]);
    }
    *reinterpret_cast<float4*>(&g_c[b * H_ + j0 + hc0]) =
        make_float4(cr[0], cr[1], cr[2], cr[3]);
    float4 hv4 = make_float4(hv[0], hv[1], hv[2], hv[3]);
    *reinterpret_cast<float4*>(&hnext[b * H_ + j0 + hc0]) = hv4;
    if (mode == 0) {
        *reinterpret_cast<float4*>(&g_h1[((size_t)b * T_ + t) * H_ + j0 + hc0]) = hv4;
    } else {
        float4 s4 = *reinterpret_cast<float4*>(&g_sum[b * H_ + j0 + hc0]);
        s4.x += hv[0]; s4.y += hv[1]; s4.z += hv[2]; s4.w += hv[3];
        *reinterpret_cast<float4*>(&g_sum[b * H_ + j0 + hc0]) = s4;
    }
}

// ---------- heads ----------
__global__ void __launch_bounds__(256) head1_kernel(
    const float* __restrict__ Wsh, const float* __restrict__ bsh)
{
    __shared__ float last[H_];
    const int b = blockIdx.x, j = threadIdx.x;
    for (int k = j; k < H_; k += 256) last[k] = g_sum[b * H_ + k] * (1.0f / (float)T_);
    __syncthreads();
    const float4* wr = reinterpret_cast<const float4*>(Wsh + (size_t)j * H_);
    const float4* lr = reinterpret_cast<const float4*>(last);
    float s = bsh[j];
#pragma unroll 4
    for (int k = 0; k < H_ / 4; k++) {
        float4 wv = wr[k], lv = lr[k];
        s += wv.x * lv.x + wv.y * lv.y + wv.z * lv.z + wv.w * lv.w;
    }
    g_head[b * 256 + j] = fmaxf(s, 0.0f) * 1.5f;
}

__global__ void __launch_bounds__(256) head2_kernel(
    const float* __restrict__ Wd, const float* __restrict__ bd,
    const float* __restrict__ Wm, const float* __restrict__ bm,
    float* __restrict__ out)
{
    const int b = threadIdx.x;
    const float4* hr = reinterpret_cast<const float4*>(g_head + b * 256);
    const float4* wd4 = reinterpret_cast<const float4*>(Wd);
    const float4* wm4 = reinterpret_cast<const float4*>(Wm);
    float sd = 0.0f, smv = 0.0f;
#pragma unroll 8
    for (int k = 0; k < 64; k++) {
        float4 h = hr[k], a = wd4[k], m = wm4[k];
        sd += h.x * a.x + h.y * a.y + h.z * a.z + h.w * a.w;
        smv += h.x * m.x + h.y * m.y + h.z * m.z + h.w * m.w;
    }
    out[b] = sd + bd[0];
    out[256 + b] = smv + bm[0];
}

// ---------- launch ----------
extern "C" void kernel_launch(void* const* d_in, const int* in_sizes, int n_in,
                              void* d_out, int out_size)
{
    (void)in_sizes; (void)n_in; (void)out_size;
    const float* x    = (const float*)d_in[0];
    const float* Wih0 = (const float*)d_in[1];
    const float* Whh0 = (const float*)d_in[2];
    const float* b0   = (const float*)d_in[3];
    const float* Wih1 = (const float*)d_in[4];
    const float* Whh1 = (const float*)d_in[5];
    const float* b1   = (const float*)d_in[6];
    const float* Wsh  = (const float*)d_in[7];
    const float* bsh  = (const float*)d_in[8];
    const float* Wdir = (const float*)d_in[9];
    const float* bdir = (const float*)d_in[10];
    const float* Wmag = (const float*)d_in[11];
    const float* bmag = (const float*)d_in[12];
    float* out = (float*)d_out;

    cudaFuncSetAttribute(lstm_step_kernel,
                         cudaFuncAttributeMaxDynamicSharedMemorySize, STEP_SMEM_BYTES);

    const dim3 gGemm(M_ALL / 128, FOURH / 64);   // (512, 32)
    const int zBlocks = (B_ * H_ + 255) / 256;

    // layer 0
    zero_state_kernel<<<zBlocks, 256>>>();
    gemm_xw_kernel<<<gGemm, 256>>>(x, 0, Wih0, b0, D_);
    for (int t = 0; t < T_; t++)
        lstm_step_kernel<<<GRID_S, 256, STEP_SMEM_BYTES>>>(Whh0, t, 0);

    // layer 1
    zero_state_kernel<<<zBlocks, 256>>>();
    gemm_xw_kernel<<<gGemm, 256>>>(nullptr, 1, Wih1, b1, H_);
    for (int t = 0; t < T_; t++)
        lstm_step_kernel<<<GRID_S, 256, STEP_SMEM_BYTES>>>(Whh1, t, 1);

    // heads
    head1_kernel<<<B_, 256>>>(Wsh, bsh);
    head2_kernel<<<1, 256>>>(Wdir, bdir, Wmag, bmag, out);
}

// round 14
// speedup vs baseline: 1.3590x; 1.3590x over previous
#include <cuda_runtime.h>
#include <cuda_fp16.h>
#include <cstdint>

#define DEVI static __device__ __forceinline__

namespace {
constexpr int B_ = 256;   // batch
constexpr int T_ = 256;   // time
constexpr int D_ = 64;    // input dim
constexpr int H_ = 512;   // hidden
constexpr int FOURH = 4 * H_;          // 2048
constexpr int M_ALL = B_ * T_;         // 65536

// step-kernel tiling: 4 batch-groups x 64 rows, 32 j-tiles x 16 cols
constexpr int MB = 64;                 // batch rows per block
constexpr int WJ = 16;                 // hidden cols per block (per gate)
constexpr int GRID_S = 128;            // 4 * 32

constexpr int G_STRIDE = 17;

// step-kernel dynamic smem: 4-stage pipeline, fp16 chunks K=64 (32 words + 4 pad)
constexpr int ST_ROWS = 64;            // rows per stage (A: 64 batch; W: 4g x 16 cols)
constexpr int ROW_W = 36;              // 32 data words (64 fp16) + 4 pad words
constexpr int ST_WORDS = ST_ROWS * ROW_W;               // 2304 words per stage
constexpr int SW_OFF = 0;                               // [4][64][36]
constexpr int SA_OFF = 4 * ST_WORDS;                    // 9216
constexpr int STEP_SMEM_WORDS = SA_OFF + 4 * ST_WORDS;  // 18432
constexpr int STEP_SMEM_BYTES = STEP_SMEM_WORDS * 4;    // 73728 B
constexpr int NCHUNK = 8;              // 8 chunks of K=64 cover H=512
}

// ---------- scratch (device globals; NO allocations anywhere) ----------
__device__ float g_xw[(size_t)M_ALL * FOURH];  // input projections, layout [t][B][4H]
__device__ float g_h1[(size_t)M_ALL * H_];     // layer-0 hidden sequence [b][t][H] (fp32)
__device__ __half g_hbf[2][B_ * H_];           // fp16 ping-pong hidden state
__device__ __half g_whf[FOURH * H_];           // fp16 recurrent weights (current layer)
__device__ float g_c[B_ * H_];                 // cell state
__device__ float g_sum[B_ * H_];               // sum over t of layer-1 h
__device__ float g_head[B_ * 256];             // shared-head output

// ---------- helpers ----------
DEVI float tf32r(float x) {
    unsigned u;
    asm("cvt.rna.tf32.f32 %0, %1;" : "=r"(u) : "f"(x));
    return __uint_as_float(u);
}

DEVI void mma8(float* c, const unsigned* a, unsigned b0, unsigned b1) {
    asm volatile(
        "mma.sync.aligned.m16n8k8.row.col.f32.tf32.tf32.f32 "
        "{%0,%1,%2,%3}, {%4,%5,%6,%7}, {%8,%9}, {%0,%1,%2,%3};\n"
        : "+f"(c[0]), "+f"(c[1]), "+f"(c[2]), "+f"(c[3])
        : "r"(a[0]), "r"(a[1]), "r"(a[2]), "r"(a[3]), "r"(b0), "r"(b1));
}

DEVI void mma16(float* c, const unsigned* a, unsigned b0, unsigned b1) {
    asm volatile(
        "mma.sync.aligned.m16n8k16.row.col.f32.f16.f16.f32 "
        "{%0,%1,%2,%3}, {%4,%5,%6,%7}, {%8,%9}, {%0,%1,%2,%3};\n"
        : "+f"(c[0]), "+f"(c[1]), "+f"(c[2]), "+f"(c[3])
        : "r"(a[0]), "r"(a[1]), "r"(a[2]), "r"(a[3]), "r"(b0), "r"(b1));
}

DEVI void cpasync16(void* dst_smem, const void* src) {
    unsigned d = (unsigned)__cvta_generic_to_shared(dst_smem);
    asm volatile("cp.async.cg.shared.global [%0], [%1], 16;\n" :: "r"(d), "l"(src));
}
DEVI void cpcommit() { asm volatile("cp.async.commit_group;\n" ::: "memory"); }
DEVI void cpwait2() { asm volatile("cp.async.wait_group 2;\n" ::: "memory"); }
DEVI void cpwait0() { asm volatile("cp.async.wait_group 0;\n" ::: "memory"); }

DEVI float sigmoidf_(float x) { return 1.0f / (1.0f + __expf(-x)); }

DEVI float tanhf_(float x) {
    x = fminf(fmaxf(x, -15.0f), 15.0f);
    float e = __expf(-2.0f * x);
    return (1.0f - e) / (1.0f + e);
}

// ---------- zero state ----------
__global__ void zero_state_kernel() {
    int i = blockIdx.x * blockDim.x + threadIdx.x;
    if (i < B_ * H_) {
        g_hbf[0][i] = __float2half(0.0f);
        g_c[i] = 0.0f;
        g_sum[i] = 0.0f;
    }
}

// ---------- fp32 -> fp16 weight conversion (one per layer; [4H][H] layout kept) ----------
__global__ void __launch_bounds__(256) conv_w_kernel(const float* __restrict__ W) {
    int i = blockIdx.x * blockDim.x + threadIdx.x;   // over FOURH*H/4 float4s
    if (i < FOURH * H_ / 4) {
        float4 v = *reinterpret_cast<const float4*>(W + (size_t)i * 4);
        __half2 h01 = __floats2half2_rn(v.x, v.y);
        __half2 h23 = __floats2half2_rn(v.z, v.w);
        uint2 u;
        u.x = *reinterpret_cast<unsigned*>(&h01);
        u.y = *reinterpret_cast<unsigned*>(&h23);
        *reinterpret_cast<uint2*>(&g_whf[(size_t)i * 4]) = u;
    }
}

// ---------- big input-projection GEMM (tf32, unchanged) ----------
// out[t][B][4H] = A[M][K] @ W[4H][K]^T + bias  (A rows m = b*T+t)
__global__ void __launch_bounds__(256) gemm_xw_kernel(
    const float* __restrict__ Aext, int useH1,
    const float* __restrict__ W, const float* __restrict__ bias, int K)
{
    __shared__ float As[128][36];
    __shared__ float Bs[64][36];
    const float* __restrict__ A = useH1 ? g_h1 : Aext;

    const int tid = threadIdx.x;
    const int lane = tid & 31;
    const int w = tid >> 5;
    const int wm = w >> 1, wn = w & 1;
    const int grp = lane >> 2, tig = lane & 3;
    const int m0 = blockIdx.x * 128;
    const int j0 = blockIdx.y * 64;

    float acc[2][4][4] = {};

    for (int kc = 0; kc < K; kc += 32) {
        __syncthreads();
#pragma unroll
        for (int i = 0; i < 4; i++) {               // A tile 128x32
            int q = tid + 256 * i;
            int r = q >> 3, c4 = (q & 7) << 2;
            float4 v = *reinterpret_cast<const float4*>(&A[(size_t)(m0 + r) * K + kc + c4]);
            As[r][c4 + 0] = tf32r(v.x);
            As[r][c4 + 1] = tf32r(v.y);
            As[r][c4 + 2] = tf32r(v.z);
            As[r][c4 + 3] = tf32r(v.w);
        }
#pragma unroll
        for (int i = 0; i < 2; i++) {               // W tile 64x32
            int q = tid + 256 * i;
            int r = q >> 3, c4 = (q & 7) << 2;
            float4 v = *reinterpret_cast<const float4*>(&W[(size_t)(j0 + r) * K + kc + c4]);
            Bs[r][c4 + 0] = tf32r(v.x);
            Bs[r][c4 + 1] = tf32r(v.y);
            Bs[r][c4 + 2] = tf32r(v.z);
            Bs[r][c4 + 3] = tf32r(v.w);
        }
        __syncthreads();

#pragma unroll
        for (int ks = 0; ks < 4; ks++) {
            unsigned a[2][4];
#pragma unroll
            for (int mt = 0; mt < 2; mt++) {
                int rb = wm * 32 + mt * 16;
                a[mt][0] = __float_as_uint(As[rb + grp][ks * 8 + tig]);
                a[mt][1] = __float_as_uint(As[rb + grp + 8][ks * 8 + tig]);
                a[mt][2] = __float_as_uint(As[rb + grp][ks * 8 + tig + 4]);
                a[mt][3] = __float_as_uint(As[rb + grp + 8][ks * 8 + tig + 4]);
            }
#pragma unroll
            for (int nt = 0; nt < 4; nt++) {
                int cb = wn * 32 + nt * 8;
                unsigned b0 = __float_as_uint(Bs[cb + grp][ks * 8 + tig]);
                unsigned b1 = __float_as_uint(Bs[cb + grp][ks * 8 + tig + 4]);
                mma8(acc[0][nt], a[0], b0, b1);
                mma8(acc[1][nt], a[1], b0, b1);
            }
        }
    }

    // epilogue: + bias, permuted write to [t][B][4H]
#pragma unroll
    for (int mt = 0; mt < 2; mt++) {
#pragma unroll
        for (int nt = 0; nt < 4; nt++) {
            int row = m0 + wm * 32 + mt * 16 + grp;
            int col = j0 + wn * 32 + nt * 8 + tig * 2;
            float bv0 = bias[col], bv1 = bias[col + 1];
#pragma unroll
            for (int half = 0; half < 2; half++) {
                int r = row + half * 8;
                int t = r & (T_ - 1), b = r >> 8;
                size_t o = ((size_t)t * B_ + b) * FOURH + col;
                g_xw[o] = acc[mt][nt][half * 2 + 0] + bv0;
                g_xw[o + 1] = acc[mt][nt][half * 2 + 1] + bv1;
            }
        }
    }
}

// ---------- one LSTM timestep (fp16 operands, K=64 chunks, 4-stage cp.async) ----------
// Grid 128 blocks: bg = bid>>5 (64 batch rows), jt = bid&31 (16 hidden cols, all 4 gates).
// 256 threads / 8 warps: warp w -> gate (w&3), batch half (w>>2).
// 8 K-chunks (64 fp16 each) stream through a 4-stage pipeline, wait_group 2, one
// __syncthreads per chunk. mma.m16n8k16.f16 with fp32 accumulate (fp16 mantissa ==
// tf32 mantissa; h, W magnitudes are far inside fp16 range).
__global__ void __launch_bounds__(256) lstm_step_kernel(
    int t, int mode)  // mode 0: write g_h1; 1: accumulate sum
{
    extern __shared__ __align__(16) unsigned smu[];
    unsigned* const SW = smu + SW_OFF;   // [4][64][36] words: stage, row (g*16+n), kpair
    unsigned* const SA = smu + SA_OFF;   // [4][64][36] words: stage, batch row, kpair

    const int tid = threadIdx.x;
    const int lane = tid & 31;
    const int w = tid >> 5;
    const int grp = lane >> 2, tig = lane & 3;
    const int bg = blockIdx.x >> 5;
    const int jt = blockIdx.x & 31;
    const int m0 = bg * MB;
    const int j0 = jt * WJ;
    const int g = w & 3;
    const int mb = (w >> 2) * 32;

    const __half* __restrict__ hprev = g_hbf[t & 1];
    __half* __restrict__ hnext = g_hbf[(t + 1) & 1];

    // ---- prefetch epilogue operands early (independent of the mainloop) ----
    const int b_loc = tid >> 2;
    const int hc0 = (tid & 3) * 4;
    const int b = m0 + b_loc;
    const size_t xo = ((size_t)t * B_ + b) * FOURH + j0 + hc0;
    const float4 xi  = __ldg(reinterpret_cast<const float4*>(&g_xw[xo]));
    const float4 xf  = __ldg(reinterpret_cast<const float4*>(&g_xw[xo + H_]));
    const float4 xg  = __ldg(reinterpret_cast<const float4*>(&g_xw[xo + 2 * H_]));
    const float4 xo4 = __ldg(reinterpret_cast<const float4*>(&g_xw[xo + 3 * H_]));
    const float4 c4  = *reinterpret_cast<const float4*>(&g_c[b * H_ + j0 + hc0]);

    // stage loader: stage s in [0,4), K element offset kc. 4 cp.async per thread.
    // seg is a word offset {0,4,...,28}; 16B = 8 fp16 at element offset seg*2.
    auto load_chunk = [&](int s, int kc) {
#pragma unroll
        for (int i = 0; i < 2; i++) {
            int p = tid + 256 * i;
            int row = p >> 3, seg = (p & 7) << 2;
            cpasync16(&SA[(s * ST_ROWS + row) * ROW_W + seg],
                      &hprev[(m0 + row) * H_ + kc + seg * 2]);
        }
#pragma unroll
        for (int i = 0; i < 2; i++) {
            int p = tid + 256 * i;
            int rw = p >> 3, seg = (p & 7) << 2;
            int g2 = rw >> 4, n = rw & 15;
            cpasync16(&SW[(s * ST_ROWS + rw) * ROW_W + seg],
                      &g_whf[(size_t)(g2 * H_ + j0 + n) * H_ + kc + seg * 2]);
        }
    };

    load_chunk(0, 0);   cpcommit();
    load_chunk(1, 64);  cpcommit();
    load_chunk(2, 128); cpcommit();

    float acc[2][2][4] = {};

    for (int ci = 0; ci < NCHUNK; ci++) {
        const int s = ci & 3;
        cpwait2();              // chunk ci resident (<=2 younger groups in flight)
        __syncthreads();        // all warps done with the stage being refilled below
        if (ci + 3 < NCHUNK) load_chunk((ci + 3) & 3, (ci + 3) * 64);
        cpcommit();             // empty tail groups keep wait arithmetic uniform

        const unsigned* Ab = &SA[s * ST_WORDS];
        const unsigned* Wb = &SW[s * ST_WORDS + (g * WJ) * ROW_W];
#pragma unroll
        for (int ks = 0; ks < 4; ks++) {            // 4 ksteps of k16 per 64-elem chunk
            unsigned a[2][4];
#pragma unroll
            for (int mt = 0; mt < 2; mt++) {
                int rb = mb + mt * 16;
                a[mt][0] = Ab[(rb + grp) * ROW_W + ks * 8 + tig];
                a[mt][1] = Ab[(rb + grp + 8) * ROW_W + ks * 8 + tig];
                a[mt][2] = Ab[(rb + grp) * ROW_W + ks * 8 + tig + 4];
                a[mt][3] = Ab[(rb + grp + 8) * ROW_W + ks * 8 + tig + 4];
            }
#pragma unroll
            for (int nt = 0; nt < 2; nt++) {
                unsigned b0 = Wb[(nt * 8 + grp) * ROW_W + ks * 8 + tig];
                unsigned b1 = Wb[(nt * 8 + grp) * ROW_W + ks * 8 + tig + 4];
                mma16(acc[0][nt], a[0], b0, b1);
                mma16(acc[1][nt], a[1], b0, b1);
            }
        }
    }
    cpwait0();   // drain empty tail groups

    // gate exchange: G (fp32) aliases SA stages 0-1 (4352 words <= 2*2304).
    // Stages 0/1 were last read at ci=4/5; every warp passed the ci=6/7 syncs.
    float* const Gsm = reinterpret_cast<float*>(&SA[0]);
#pragma unroll
    for (int mt = 0; mt < 2; mt++) {
#pragma unroll
        for (int nt = 0; nt < 2; nt++) {
            int r0 = mb + mt * 16 + grp;
            int c = nt * 8 + tig * 2;
            Gsm[(g * MB + r0) * G_STRIDE + c] = acc[mt][nt][0];
            Gsm[(g * MB + r0) * G_STRIDE + c + 1] = acc[mt][nt][1];
            Gsm[(g * MB + r0 + 8) * G_STRIDE + c] = acc[mt][nt][2];
            Gsm[(g * MB + r0 + 8) * G_STRIDE + c + 1] = acc[mt][nt][3];
        }
    }
    __syncthreads();

    // fused activation + cell update: 4 cells per thread
    float gi[4] = {xi.x, xi.y, xi.z, xi.w};
    float gf[4] = {xf.x, xf.y, xf.z, xf.w};
    float gg[4] = {xg.x, xg.y, xg.z, xg.w};
    float go[4] = {xo4.x, xo4.y, xo4.z, xo4.w};
    float cr[4] = {c4.x, c4.y, c4.z, c4.w};
    float hv[4];
#pragma unroll
    for (int j = 0; j < 4; j++) {
        int gb = b_loc * G_STRIDE + hc0 + j;
        float ii = sigmoidf_(Gsm[gb] + gi[j]);
        float ff = sigmoidf_(Gsm[MB * G_STRIDE + gb] + gf[j]);
        float gt = tanhf_(Gsm[2 * MB * G_STRIDE + gb] + gg[j]);
        float oo = sigmoidf_(Gsm[3 * MB * G_STRIDE + gb] + go[j]);
        cr[j] = ff * cr[j] + ii * gt;
        hv[j] = oo * tanhf_(cr[j]);
    }
    *reinterpret_cast<float4*>(&g_c[b * H_ + j0 + hc0]) =
        make_float4(cr[0], cr[1], cr[2], cr[3]);

    // fp16 h for the next step's A operand
    __half2 h01 = __floats2half2_rn(hv[0], hv[1]);
    __half2 h23 = __floats2half2_rn(hv[2], hv[3]);
    uint2 hu;
    hu.x = *reinterpret_cast<unsigned*>(&h01);
    hu.y = *reinterpret_cast<unsigned*>(&h23);
    *reinterpret_cast<uint2*>(&hnext[b * H_ + j0 + hc0]) = hu;

    if (mode == 0) {
        *reinterpret_cast<float4*>(&g_h1[((size_t)b * T_ + t) * H_ + j0 + hc0]) =
            make_float4(hv[0], hv[1], hv[2], hv[3]);
    } else {
        float4 s4 = *reinterpret_cast<float4*>(&g_sum[b * H_ + j0 + hc0]);
        s4.x += hv[0]; s4.y += hv[1]; s4.z += hv[2]; s4.w += hv[3];
        *reinterpret_cast<float4*>(&g_sum[b * H_ + j0 + hc0]) = s4;
    }
}

// ---------- heads ----------
__global__ void __launch_bounds__(256) head1_kernel(
    const float* __restrict__ Wsh, const float* __restrict__ bsh)
{
    __shared__ float last[H_];
    const int b = blockIdx.x, j = threadIdx.x;
    for (int k = j; k < H_; k += 256) last[k] = g_sum[b * H_ + k] * (1.0f / (float)T_);
    __syncthreads();
    const float4* wr = reinterpret_cast<const float4*>(Wsh + (size_t)j * H_);
    const float4* lr = reinterpret_cast<const float4*>(last);
    float s = bsh[j];
#pragma unroll 4
    for (int k = 0; k < H_ / 4; k++) {
        float4 wv = wr[k], lv = lr[k];
        s += wv.x * lv.x + wv.y * lv.y + wv.z * lv.z + wv.w * lv.w;
    }
    g_head[b * 256 + j] = fmaxf(s, 0.0f) * 1.5f;
}

__global__ void __launch_bounds__(256) head2_kernel(
    const float* __restrict__ Wd, const float* __restrict__ bd,
    const float* __restrict__ Wm, const float* __restrict__ bm,
    float* __restrict__ out)
{
    const int b = threadIdx.x;
    const float4* hr = reinterpret_cast<const float4*>(g_head + b * 256);
    const float4* wd4 = reinterpret_cast<const float4*>(Wd);
    const float4* wm4 = reinterpret_cast<const float4*>(Wm);
    float sd = 0.0f, smv = 0.0f;
#pragma unroll 8
    for (int k = 0; k < 64; k++) {
        float4 h = hr[k], a = wd4[k], m = wm4[k];
        sd += h.x * a.x + h.y * a.y + h.z * a.z + h.w * a.w;
        smv += h.x * m.x + h.y * m.y + h.z * m.z + h.w * m.w;
    }
    out[b] = sd + bd[0];
    out[256 + b] = smv + bm[0];
}

// ---------- launch ----------
extern "C" void kernel_launch(void* const* d_in, const int* in_sizes, int n_in,
                              void* d_out, int out_size)
{
    (void)in_sizes; (void)n_in; (void)out_size;
    const float* x    = (const float*)d_in[0];
    const float* Wih0 = (const float*)d_in[1];
    const float* Whh0 = (const float*)d_in[2];
    const float* b0   = (const float*)d_in[3];
    const float* Wih1 = (const float*)d_in[4];
    const float* Whh1 = (const float*)d_in[5];
    const float* b1   = (const float*)d_in[6];
    const float* Wsh  = (const float*)d_in[7];
    const float* bsh  = (const float*)d_in[8];
    const float* Wdir = (const float*)d_in[9];
    const float* bdir = (const float*)d_in[10];
    const float* Wmag = (const float*)d_in[11];
    const float* bmag = (const float*)d_in[12];
    float* out = (float*)d_out;

    cudaFuncSetAttribute(lstm_step_kernel,
                         cudaFuncAttributeMaxDynamicSharedMemorySize, STEP_SMEM_BYTES);

    const dim3 gGemm(M_ALL / 128, FOURH / 64);   // (512, 32)
    const int zBlocks = (B_ * H_ + 255) / 256;
    const int cBlocks = (FOURH * H_ / 4 + 255) / 256;

    // layer 0
    zero_state_kernel<<<zBlocks, 256>>>();
    conv_w_kernel<<<cBlocks, 256>>>(Whh0);
    gemm_xw_kernel<<<gGemm, 256>>>(x, 0, Wih0, b0, D_);
    for (int t = 0; t < T_; t++)
        lstm_step_kernel<<<GRID_S, 256, STEP_SMEM_BYTES>>>(t, 0);

    // layer 1
    zero_state_kernel<<<zBlocks, 256>>>();
    conv_w_kernel<<<cBlocks, 256>>>(Whh1);
    gemm_xw_kernel<<<gGemm, 256>>>(nullptr, 1, Wih1, b1, H_);
    for (int t = 0; t < T_; t++)
        lstm_step_kernel<<<GRID_S, 256, STEP_SMEM_BYTES>>>(t, 1);

    // heads
    head1_kernel<<<B_, 256>>>(Wsh, bsh);
    head2_kernel<<<1, 256>>>(Wdir, bdir, Wmag, bmag, out);
}

// round 15
// speedup vs baseline: 1.4516x; 1.0681x over previous
#include <cuda_runtime.h>
#include <cuda_fp16.h>
#include <cstdint>

#define DEVI static __device__ __forceinline__

namespace {
constexpr int B_ = 256;   // batch
constexpr int T_ = 256;   // time
constexpr int D_ = 64;    // input dim
constexpr int H_ = 512;   // hidden
constexpr int FOURH = 4 * H_;          // 2048
constexpr int M_ALL = B_ * T_;         // 65536

// step-kernel tiling: 4 batch-groups x 64 rows, 32 j-tiles x 16 cols
constexpr int MB = 64;                 // batch rows per block
constexpr int WJ = 16;                 // hidden cols per block (per gate)
constexpr int GRID_S = 128;            // 4 * 32
constexpr int THR_S = 512;             // 16 warps: gate (4) x batch-quarter (4)

constexpr int G_STRIDE = 17;

// step-kernel dynamic smem: 4-stage pipeline, fp16 chunks K=64 (32 words + 4 pad)
constexpr int ST_ROWS = 64;            // rows per stage (A: 64 batch; W: 4g x 16 cols)
constexpr int ROW_W = 36;              // 32 data words (64 fp16) + 4 pad words
constexpr int ST_WORDS = ST_ROWS * ROW_W;               // 2304 words per stage
constexpr int SW_OFF = 0;                               // [4][64][36]
constexpr int SA_OFF = 4 * ST_WORDS;                    // 9216
constexpr int STEP_SMEM_WORDS = SA_OFF + 4 * ST_WORDS;  // 18432
constexpr int STEP_SMEM_BYTES = STEP_SMEM_WORDS * 4;    // 73728 B
constexpr int NCHUNK = 8;              // 8 chunks of K=64 cover H=512
}

// ---------- scratch (device globals; NO allocations anywhere) ----------
__device__ float g_xw[(size_t)M_ALL * FOURH];  // input projections, layout [t][B][4H]
__device__ float g_h1[(size_t)M_ALL * H_];     // layer-0 hidden sequence [b][t][H] (fp32)
__device__ __half g_hbf[2][B_ * H_];           // fp16 ping-pong hidden state
__device__ __half g_whf[FOURH * H_];           // fp16 recurrent weights (current layer)
__device__ float g_c[B_ * H_];                 // cell state
__device__ float g_sum[B_ * H_];               // sum over t of layer-1 h
__device__ float g_head[B_ * 256];             // shared-head output

// ---------- helpers ----------
DEVI float tf32r(float x) {
    unsigned u;
    asm("cvt.rna.tf32.f32 %0, %1;" : "=r"(u) : "f"(x));
    return __uint_as_float(u);
}

DEVI void mma8(float* c, const unsigned* a, unsigned b0, unsigned b1) {
    asm volatile(
        "mma.sync.aligned.m16n8k8.row.col.f32.tf32.tf32.f32 "
        "{%0,%1,%2,%3}, {%4,%5,%6,%7}, {%8,%9}, {%0,%1,%2,%3};\n"
        : "+f"(c[0]), "+f"(c[1]), "+f"(c[2]), "+f"(c[3])
        : "r"(a[0]), "r"(a[1]), "r"(a[2]), "r"(a[3]), "r"(b0), "r"(b1));
}

DEVI void mma16(float* c, const unsigned* a, unsigned b0, unsigned b1) {
    asm volatile(
        "mma.sync.aligned.m16n8k16.row.col.f32.f16.f16.f32 "
        "{%0,%1,%2,%3}, {%4,%5,%6,%7}, {%8,%9}, {%0,%1,%2,%3};\n"
        : "+f"(c[0]), "+f"(c[1]), "+f"(c[2]), "+f"(c[3])
        : "r"(a[0]), "r"(a[1]), "r"(a[2]), "r"(a[3]), "r"(b0), "r"(b1));
}

DEVI void cpasync16(void* dst_smem, const void* src) {
    unsigned d = (unsigned)__cvta_generic_to_shared(dst_smem);
    asm volatile("cp.async.cg.shared.global [%0], [%1], 16;\n" :: "r"(d), "l"(src));
}
DEVI void cpcommit() { asm volatile("cp.async.commit_group;\n" ::: "memory"); }
DEVI void cpwait2() { asm volatile("cp.async.wait_group 2;\n" ::: "memory"); }
DEVI void cpwait0() { asm volatile("cp.async.wait_group 0;\n" ::: "memory"); }

DEVI float sigmoidf_(float x) { return 1.0f / (1.0f + __expf(-x)); }

DEVI float tanhf_(float x) {
    x = fminf(fmaxf(x, -15.0f), 15.0f);
    float e = __expf(-2.0f * x);
    return (1.0f - e) / (1.0f + e);
}

// ---------- zero state ----------
__global__ void zero_state_kernel() {
    int i = blockIdx.x * blockDim.x + threadIdx.x;
    if (i < B_ * H_) {
        g_hbf[0][i] = __float2half(0.0f);
        g_c[i] = 0.0f;
        g_sum[i] = 0.0f;
    }
}

// ---------- fp32 -> fp16 weight conversion (one per layer; [4H][H] layout kept) ----------
__global__ void __launch_bounds__(256) conv_w_kernel(const float* __restrict__ W) {
    int i = blockIdx.x * blockDim.x + threadIdx.x;   // over FOURH*H/4 float4s
    if (i < FOURH * H_ / 4) {
        float4 v = *reinterpret_cast<const float4*>(W + (size_t)i * 4);
        __half2 h01 = __floats2half2_rn(v.x, v.y);
        __half2 h23 = __floats2half2_rn(v.z, v.w);
        uint2 u;
        u.x = *reinterpret_cast<unsigned*>(&h01);
        u.y = *reinterpret_cast<unsigned*>(&h23);
        *reinterpret_cast<uint2*>(&g_whf[(size_t)i * 4]) = u;
    }
}

// ---------- big input-projection GEMM (tf32, unchanged) ----------
// out[t][B][4H] = A[M][K] @ W[4H][K]^T + bias  (A rows m = b*T+t)
__global__ void __launch_bounds__(256) gemm_xw_kernel(
    const float* __restrict__ Aext, int useH1,
    const float* __restrict__ W, const float* __restrict__ bias, int K)
{
    __shared__ float As[128][36];
    __shared__ float Bs[64][36];
    const float* __restrict__ A = useH1 ? g_h1 : Aext;

    const int tid = threadIdx.x;
    const int lane = tid & 31;
    const int w = tid >> 5;
    const int wm = w >> 1, wn = w & 1;
    const int grp = lane >> 2, tig = lane & 3;
    const int m0 = blockIdx.x * 128;
    const int j0 = blockIdx.y * 64;

    float acc[2][4][4] = {};

    for (int kc = 0; kc < K; kc += 32) {
        __syncthreads();
#pragma unroll
        for (int i = 0; i < 4; i++) {               // A tile 128x32
            int q = tid + 256 * i;
            int r = q >> 3, c4 = (q & 7) << 2;
            float4 v = *reinterpret_cast<const float4*>(&A[(size_t)(m0 + r) * K + kc + c4]);
            As[r][c4 + 0] = tf32r(v.x);
            As[r][c4 + 1] = tf32r(v.y);
            As[r][c4 + 2] = tf32r(v.z);
            As[r][c4 + 3] = tf32r(v.w);
        }
#pragma unroll
        for (int i = 0; i < 2; i++) {               // W tile 64x32
            int q = tid + 256 * i;
            int r = q >> 3, c4 = (q & 7) << 2;
            float4 v = *reinterpret_cast<const float4*>(&W[(size_t)(j0 + r) * K + kc + c4]);
            Bs[r][c4 + 0] = tf32r(v.x);
            Bs[r][c4 + 1] = tf32r(v.y);
            Bs[r][c4 + 2] = tf32r(v.z);
            Bs[r][c4 + 3] = tf32r(v.w);
        }
        __syncthreads();

#pragma unroll
        for (int ks = 0; ks < 4; ks++) {
            unsigned a[2][4];
#pragma unroll
            for (int mt = 0; mt < 2; mt++) {
                int rb = wm * 32 + mt * 16;
                a[mt][0] = __float_as_uint(As[rb + grp][ks * 8 + tig]);
                a[mt][1] = __float_as_uint(As[rb + grp + 8][ks * 8 + tig]);
                a[mt][2] = __float_as_uint(As[rb + grp][ks * 8 + tig + 4]);
                a[mt][3] = __float_as_uint(As[rb + grp + 8][ks * 8 + tig + 4]);
            }
#pragma unroll
            for (int nt = 0; nt < 4; nt++) {
                int cb = wn * 32 + nt * 8;
                unsigned b0 = __float_as_uint(Bs[cb + grp][ks * 8 + tig]);
                unsigned b1 = __float_as_uint(Bs[cb + grp][ks * 8 + tig + 4]);
                mma8(acc[0][nt], a[0], b0, b1);
                mma8(acc[1][nt], a[1], b0, b1);
            }
        }
    }

    // epilogue: + bias, permuted write to [t][B][4H]
#pragma unroll
    for (int mt = 0; mt < 2; mt++) {
#pragma unroll
        for (int nt = 0; nt < 4; nt++) {
            int row = m0 + wm * 32 + mt * 16 + grp;
            int col = j0 + wn * 32 + nt * 8 + tig * 2;
            float bv0 = bias[col], bv1 = bias[col + 1];
#pragma unroll
            for (int half = 0; half < 2; half++) {
                int r = row + half * 8;
                int t = r & (T_ - 1), b = r >> 8;
                size_t o = ((size_t)t * B_ + b) * FOURH + col;
                g_xw[o] = acc[mt][nt][half * 2 + 0] + bv0;
                g_xw[o + 1] = acc[mt][nt][half * 2 + 1] + bv1;
            }
        }
    }
}

// ---------- one LSTM timestep (fp16, K=64 chunks, 4-stage cp.async, 16 warps) ----------
// Grid 128 blocks: bg = bid>>5 (64 batch rows), jt = bid&31 (16 hidden cols, all 4 gates).
// 512 threads / 16 warps: warp w -> gate (w&3), batch-quarter (w>>2, 16 rows).
// Same smem layout & global traffic as the 8-warp version; 2x schedulable warps per
// SMSP to hide cp.async/LDS/mma latency (kernel was occupancy/latency-bound).
__global__ void __launch_bounds__(THR_S) lstm_step_kernel(
    int t, int mode)  // mode 0: write g_h1; 1: accumulate sum
{
    extern __shared__ __align__(16) unsigned smu[];
    unsigned* const SW = smu + SW_OFF;   // [4][64][36] words: stage, row (g*16+n), kpair
    unsigned* const SA = smu + SA_OFF;   // [4][64][36] words: stage, batch row, kpair

    const int tid = threadIdx.x;
    const int lane = tid & 31;
    const int w = tid >> 5;
    const int grp = lane >> 2, tig = lane & 3;
    const int bg = blockIdx.x >> 5;
    const int jt = blockIdx.x & 31;
    const int m0 = bg * MB;
    const int j0 = jt * WJ;
    const int g = w & 3;
    const int mb = (w >> 2) * 16;        // batch-quarter base row

    const __half* __restrict__ hprev = g_hbf[t & 1];
    __half* __restrict__ hnext = g_hbf[(t + 1) & 1];

    // ---- prefetch epilogue operands early (2 cells per thread) ----
    const int b_loc = tid >> 3;          // 0..63
    const int hc0 = (tid & 7) * 2;       // 0..14
    const int b = m0 + b_loc;
    const size_t xo = ((size_t)t * B_ + b) * FOURH + j0 + hc0;
    const float2 xi  = __ldg(reinterpret_cast<const float2*>(&g_xw[xo]));
    const float2 xf  = __ldg(reinterpret_cast<const float2*>(&g_xw[xo + H_]));
    const float2 xg  = __ldg(reinterpret_cast<const float2*>(&g_xw[xo + 2 * H_]));
    const float2 xo2 = __ldg(reinterpret_cast<const float2*>(&g_xw[xo + 3 * H_]));
    const float2 c2  = *reinterpret_cast<const float2*>(&g_c[b * H_ + j0 + hc0]);

    // stage loader: 2 cp.async per thread (A: 1, W: 1); 512 float4 each
    auto load_chunk = [&](int s, int kc) {
        {
            int row = tid >> 3, seg = (tid & 7) << 2;
            cpasync16(&SA[(s * ST_ROWS + row) * ROW_W + seg],
                      &hprev[(m0 + row) * H_ + kc + seg * 2]);
        }
        {
            int rw = tid >> 3, seg = (tid & 7) << 2;
            int g2 = rw >> 4, n = rw & 15;
            cpasync16(&SW[(s * ST_ROWS + rw) * ROW_W + seg],
                      &g_whf[(size_t)(g2 * H_ + j0 + n) * H_ + kc + seg * 2]);
        }
    };

    load_chunk(0, 0);   cpcommit();
    load_chunk(1, 64);  cpcommit();
    load_chunk(2, 128); cpcommit();

    float acc[2][4] = {};

    for (int ci = 0; ci < NCHUNK; ci++) {
        const int s = ci & 3;
        cpwait2();              // chunk ci resident (<=2 younger groups in flight)
        __syncthreads();        // all warps done with the stage being refilled below
        if (ci + 3 < NCHUNK) load_chunk((ci + 3) & 3, (ci + 3) * 64);
        cpcommit();             // empty tail groups keep wait arithmetic uniform

        const unsigned* Ab = &SA[s * ST_WORDS];
        const unsigned* Wb = &SW[s * ST_WORDS + (g * WJ) * ROW_W];
#pragma unroll
        for (int ks = 0; ks < 4; ks++) {            // 4 ksteps of k16 per 64-elem chunk
            unsigned a[4];
            a[0] = Ab[(mb + grp) * ROW_W + ks * 8 + tig];
            a[1] = Ab[(mb + grp + 8) * ROW_W + ks * 8 + tig];
            a[2] = Ab[(mb + grp) * ROW_W + ks * 8 + tig + 4];
            a[3] = Ab[(mb + grp + 8) * ROW_W + ks * 8 + tig + 4];
#pragma unroll
            for (int nt = 0; nt < 2; nt++) {
                unsigned b0 = Wb[(nt * 8 + grp) * ROW_W + ks * 8 + tig];
                unsigned b1 = Wb[(nt * 8 + grp) * ROW_W + ks * 8 + tig + 4];
                mma16(acc[nt], a, b0, b1);
            }
        }
    }
    cpwait0();   // drain empty tail groups

    // gate exchange: G (fp32) aliases SA stages 0-1 (4352 words <= 2*2304).
    // Stages 0/1 last read at ci=4/5; every warp passed the ci=6/7 top-of-loop syncs.
    float* const Gsm = reinterpret_cast<float*>(&SA[0]);
#pragma unroll
    for (int nt = 0; nt < 2; nt++) {
        int r0 = mb + grp;
        int c = nt * 8 + tig * 2;
        Gsm[(g * MB + r0) * G_STRIDE + c]     = acc[nt][0];
        Gsm[(g * MB + r0) * G_STRIDE + c + 1] = acc[nt][1];
        Gsm[(g * MB + r0 + 8) * G_STRIDE + c]     = acc[nt][2];
        Gsm[(g * MB + r0 + 8) * G_STRIDE + c + 1] = acc[nt][3];
    }
    __syncthreads();

    // fused activation + cell update: 2 cells per thread
    float gi[2] = {xi.x, xi.y};
    float gf[2] = {xf.x, xf.y};
    float gg[2] = {xg.x, xg.y};
    float go[2] = {xo2.x, xo2.y};
    float cr[2] = {c2.x, c2.y};
    float hv[2];
#pragma unroll
    for (int j = 0; j < 2; j++) {
        int gb = b_loc * G_STRIDE + hc0 + j;
        float ii = sigmoidf_(Gsm[gb] + gi[j]);
        float ff = sigmoidf_(Gsm[MB * G_STRIDE + gb] + gf[j]);
        float gt = tanhf_(Gsm[2 * MB * G_STRIDE + gb] + gg[j]);
        float oo = sigmoidf_(Gsm[3 * MB * G_STRIDE + gb] + go[j]);
        cr[j] = ff * cr[j] + ii * gt;
        hv[j] = oo * tanhf_(cr[j]);
    }
    *reinterpret_cast<float2*>(&g_c[b * H_ + j0 + hc0]) = make_float2(cr[0], cr[1]);

    // fp16 h for the next step's A operand
    __half2 h01 = __floats2half2_rn(hv[0], hv[1]);
    *reinterpret_cast<unsigned*>(&hnext[b * H_ + j0 + hc0]) =
        *reinterpret_cast<unsigned*>(&h01);

    if (mode == 0) {
        *reinterpret_cast<float2*>(&g_h1[((size_t)b * T_ + t) * H_ + j0 + hc0]) =
            make_float2(hv[0], hv[1]);
    } else {
        float2 s2 = *reinterpret_cast<float2*>(&g_sum[b * H_ + j0 + hc0]);
        s2.x += hv[0]; s2.y += hv[1];
        *reinterpret_cast<float2*>(&g_sum[b * H_ + j0 + hc0]) = s2;
    }
}

// ---------- heads ----------
__global__ void __launch_bounds__(256) head1_kernel(
    const float* __restrict__ Wsh, const float* __restrict__ bsh)
{
    __shared__ float last[H_];
    const int b = blockIdx.x, j = threadIdx.x;
    for (int k = j; k < H_; k += 256) last[k] = g_sum[b * H_ + k] * (1.0f / (float)T_);
    __syncthreads();
    const float4* wr = reinterpret_cast<const float4*>(Wsh + (size_t)j * H_);
    const float4* lr = reinterpret_cast<const float4*>(last);
    float s = bsh[j];
#pragma unroll 4
    for (int k = 0; k < H_ / 4; k++) {
        float4 wv = wr[k], lv = lr[k];
        s += wv.x * lv.x + wv.y * lv.y + wv.z * lv.z + wv.w * lv.w;
    }
    g_head[b * 256 + j] = fmaxf(s, 0.0f) * 1.5f;
}

__global__ void __launch_bounds__(256) head2_kernel(
    const float* __restrict__ Wd, const float* __restrict__ bd,
    const float* __restrict__ Wm, const float* __restrict__ bm,
    float* __restrict__ out)
{
    const int b = threadIdx.x;
    const float4* hr = reinterpret_cast<const float4*>(g_head + b * 256);
    const float4* wd4 = reinterpret_cast<const float4*>(Wd);
    const float4* wm4 = reinterpret_cast<const float4*>(Wm);
    float sd = 0.0f, smv = 0.0f;
#pragma unroll 8
    for (int k = 0; k < 64; k++) {
        float4 h = hr[k], a = wd4[k], m = wm4[k];
        sd += h.x * a.x + h.y * a.y + h.z * a.z + h.w * a.w;
        smv += h.x * m.x + h.y * m.y + h.z * m.z + h.w * m.w;
    }
    out[b] = sd + bd[0];
    out[256 + b] = smv + bm[0];
}

// ---------- launch ----------
extern "C" void kernel_launch(void* const* d_in, const int* in_sizes, int n_in,
                              void* d_out, int out_size)
{
    (void)in_sizes; (void)n_in; (void)out_size;
    const float* x    = (const float*)d_in[0];
    const float* Wih0 = (const float*)d_in[1];
    const float* Whh0 = (const float*)d_in[2];
    const float* b0   = (const float*)d_in[3];
    const float* Wih1 = (const float*)d_in[4];
    const float* Whh1 = (const float*)d_in[5];
    const float* b1   = (const float*)d_in[6];
    const float* Wsh  = (const float*)d_in[7];
    const float* bsh  = (const float*)d_in[8];
    const float* Wdir = (const float*)d_in[9];
    const float* bdir = (const float*)d_in[10];
    const float* Wmag = (const float*)d_in[11];
    const float* bmag = (const float*)d_in[12];
    float* out = (float*)d_out;

    cudaFuncSetAttribute(lstm_step_kernel,
                         cudaFuncAttributeMaxDynamicSharedMemorySize, STEP_SMEM_BYTES);

    const dim3 gGemm(M_ALL / 128, FOURH / 64);   // (512, 32)
    const int zBlocks = (B_ * H_ + 255) / 256;
    const int cBlocks = (FOURH * H_ / 4 + 255) / 256;

    // layer 0
    zero_state_kernel<<<zBlocks, 256>>>();
    conv_w_kernel<<<cBlocks, 256>>>(Whh0);
    gemm_xw_kernel<<<gGemm, 256>>>(x, 0, Wih0, b0, D_);
    for (int t = 0; t < T_; t++)
        lstm_step_kernel<<<GRID_S, THR_S, STEP_SMEM_BYTES>>>(t, 0);

    // layer 1
    zero_state_kernel<<<zBlocks, 256>>>();
    conv_w_kernel<<<cBlocks, 256>>>(Whh1);
    gemm_xw_kernel<<<gGemm, 256>>>(nullptr, 1, Wih1, b1, H_);
    for (int t = 0; t < T_; t++)
        lstm_step_kernel<<<GRID_S, THR_S, STEP_SMEM_BYTES>>>(t, 1);

    // heads
    head1_kernel<<<B_, 256>>>(Wsh, bsh);
    head2_kernel<<<1, 256>>>(Wdir, bdir, Wmag, bmag, out);
}